// round 2
// baseline (speedup 1.0000x reference)
#include <cuda_runtime.h>
#include <cstddef>

#define Bq 256
#define Sq 4096
#define Hq 64
#define Cq 32            // chunks along S
#define Lq (Sq / Cq)     // 128 elements per chunk

// Inter-block chained-scan scratch: inclusive prefixes + ready flags.
__device__ float    g_inc[(size_t)Bq * Cq * Hq];   // 2 MB
__device__ unsigned g_flag[Bq * Cq];               // 32 KB, memset to 0 each launch

__global__ void __launch_bounds__(Hq) k_fused(const float* __restrict__ x,
                                              const float* __restrict__ W_e,
                                              const float* __restrict__ b_e,
                                              const float* __restrict__ omega,
                                              const float* __restrict__ W_r,
                                              const float* __restrict__ b_r,
                                              float* __restrict__ out,
                                              float* __restrict__ hseq) {
    __shared__ float shx[Lq];
    const int bc = blockIdx.x;          // b*Cq + c
    const int h  = threadIdx.x;
    const int b  = bc >> 5;
    const int c  = bc & (Cq - 1);

    // Stage the x chunk once (both passes read it as LDS broadcast).
    const float* xc = x + (size_t)b * Sq + (size_t)c * Lq;
    shx[h]      = xc[h];
    shx[h + Hq] = xc[h + Hq];

    // Turns-space wrap: delta = 2*pi*(u - rint(u)), u = (x*we + be)/(2*pi).
    const float INV_2PI = 0.15915494309189535f;
    const float TWO_PI  = 6.283185307179586f;
    const float we2 = W_e[h]   * INV_2PI;
    const float be2 = b_e[h]   * INV_2PI;
    const float om2 = omega[h] * TWO_PI;
    __syncthreads();

    // ---- pass 1: chunk aggregate (no stores) ----
    float agg = 0.0f;
#pragma unroll 16
    for (int s = 0; s < Lq; ++s) {
        float u = fmaf(shx[s], we2, be2);
        float f = u - rintf(u);
        agg = fmaf(om2, f, agg);
    }

    // ---- chained carry: wait on predecessor's inclusive prefix ----
    float carry = 0.0f;
    if (c > 0) {
        if (h == 0) {
            const unsigned* fp = &g_flag[bc - 1];
            unsigned v;
            while (true) {
                asm volatile("ld.global.acquire.gpu.u32 %0, [%1];"
                             : "=r"(v) : "l"(fp) : "memory");
                if (v) break;
                __nanosleep(50);
            }
        }
        __syncthreads();
        carry = __ldcg(&g_inc[(size_t)(bc - 1) * Hq + h]);
    }
    // Publish our inclusive prefix ASAP so the chain runs ahead of pass 2.
    if (c < Cq - 1) {
        g_inc[(size_t)bc * Hq + h] = carry + agg;
        __syncthreads();
        if (h == 0) {
            __threadfence();
            asm volatile("st.global.release.gpu.u32 [%0], %1;"
                         :: "l"(&g_flag[bc]), "r"(1u) : "memory");
        }
    }

    // ---- pass 2: carry-seeded scan, streaming Hseq out ----
    float acc = carry;
    float* hp = hseq + ((size_t)b * Sq + (size_t)c * Lq) * Hq + h;
#pragma unroll 16
    for (int s = 0; s < Lq; ++s) {
        float u = fmaf(shx[s], we2, be2);
        float f = u - rintf(u);
        acc = fmaf(om2, f, acc);
        __stcs(hp + (size_t)s * Hq, acc);
    }

    // ---- fused output head: last chunk's final acc == ph[b][h] ----
    if (c == Cq - 1) {
        float ph = acc;
        float t = ph * W_r[2 * Hq + h];
        t = fmaf(cosf(ph), W_r[h], t);
        t = fmaf(sinf(ph), W_r[Hq + h], t);
#pragma unroll
        for (int o = 16; o > 0; o >>= 1)
            t += __shfl_down_sync(0xffffffffu, t, o);
        __shared__ float sh2[2];
        if ((h & 31) == 0) sh2[h >> 5] = t;
        __syncthreads();
        if (h == 0) out[b] = sh2[0] + sh2[1] + b_r[0];
    }
}

extern "C" void kernel_launch(void* const* d_in, const int* in_sizes, int n_in,
                              void* d_out, int out_size) {
    const float* x     = (const float*)d_in[0];
    const float* W_e   = (const float*)d_in[1];
    const float* b_e   = (const float*)d_in[2];
    const float* omega = (const float*)d_in[3];
    const float* W_r   = (const float*)d_in[4];
    const float* b_r   = (const float*)d_in[5];

    float* out  = (float*)d_out;        // out = B floats
    float* hseq = (float*)d_out + Bq;   // then Hseq = B*S*H floats

    // Reset chain flags every launch (graph-capturable async memset).
    unsigned* flags = nullptr;
    cudaGetSymbolAddress((void**)&flags, g_flag);
    cudaMemsetAsync(flags, 0, sizeof(unsigned) * Bq * Cq);

    k_fused<<<Bq * Cq, Hq>>>(x, W_e, b_e, omega, W_r, b_r, out, hseq);
}

// round 3
// speedup vs baseline: 1.6864x; 1.6864x over previous
#include <cuda_runtime.h>
#include <cstddef>

#define Bq 256
#define Sq 4096
#define Hq 64
#define Cq 32            // chunks along S
#define Lq (Sq / Cq)     // 128 elements per chunk

// Per-(b,chunk,h) chunk aggregates of omega*delta. 2 MB -> L2-resident.
__device__ float g_part[(size_t)Bq * Cq * Hq];

// ---------------- Phase 1: chunk aggregates via separability ----------------
// agg(b,c,h) = om*2pi * ( we2*Sum(x) + L*be2 - Sum_s rint(u_s) ),
// u_s = fma(x_s, we2, be2), we2 = W_e/2pi, be2 = b_e/2pi.
__global__ void __launch_bounds__(Hq) k_partials(const float* __restrict__ x,
                                                 const float* __restrict__ W_e,
                                                 const float* __restrict__ b_e,
                                                 const float* __restrict__ omega) {
    __shared__ float shx[Lq];
    __shared__ float s_red[2];
    const int bc = blockIdx.x;          // b*Cq + c
    const int h  = threadIdx.x;
    const int b  = bc >> 5;
    const int c  = bc & (Cq - 1);

    const float* xc = x + (size_t)b * Sq + (size_t)c * Lq;
    float v0 = xc[h], v1 = xc[h + Hq];
    shx[h] = v0; shx[h + Hq] = v1;

    const float INV_2PI = 0.15915494309189535f;
    const float TWO_PI  = 6.283185307179586f;
    const float we2 = W_e[h]   * INV_2PI;
    const float be2 = b_e[h]   * INV_2PI;
    const float om2 = omega[h] * TWO_PI;

    // Cooperative Sum(x) over the chunk (exact same value for all h).
    float ps = v0 + v1;
#pragma unroll
    for (int o = 16; o > 0; o >>= 1) ps += __shfl_down_sync(0xffffffffu, ps, o);
    if ((h & 31) == 0) s_red[h >> 5] = ps;
    __syncthreads();
    const float sx = s_red[0] + s_red[1];

    // Sum of rints (integers -> exact).
    float racc = 0.0f;
#pragma unroll 16
    for (int s = 0; s < Lq; ++s) {
        float u = fmaf(shx[s], we2, be2);
        racc += rintf(u);
    }
    float agg = om2 * (fmaf(we2, sx, (float)Lq * be2) - racc);
    g_part[(size_t)bc * Hq + h] = agg;
}

// ---------------- Phase 2: fused prefix + scan + output head ----------------
__global__ void __launch_bounds__(Hq) k_scan(const float* __restrict__ x,
                                             const float* __restrict__ W_e,
                                             const float* __restrict__ b_e,
                                             const float* __restrict__ omega,
                                             const float* __restrict__ W_r,
                                             const float* __restrict__ b_r,
                                             float* __restrict__ out,
                                             float* __restrict__ hseq) {
    __shared__ float shx[Lq];
    const int bc = blockIdx.x;          // b*Cq + c
    const int h  = threadIdx.x;
    const int b  = bc >> 5;
    const int c  = bc & (Cq - 1);

    const float* xc = x + (size_t)b * Sq + (size_t)c * Lq;
    shx[h]      = xc[h];
    shx[h + Hq] = xc[h + Hq];

    const float INV_2PI = 0.15915494309189535f;
    const float TWO_PI  = 6.283185307179586f;
    const float we2 = W_e[h]   * INV_2PI;
    const float be2 = b_e[h]   * INV_2PI;
    const float om2 = omega[h] * TWO_PI;

    // Carry = sum of predecessor chunk aggregates (L2-resident loads).
    float carry = 0.0f;
    const float* gp = &g_part[(size_t)(b << 5) * Hq + h];
    for (int cc = 0; cc < c; ++cc)
        carry += __ldg(gp + (size_t)cc * Hq);
    __syncthreads();

    // Carry-seeded scan, streaming Hseq.
    float acc = carry;
    float* hp = hseq + ((size_t)b * Sq + (size_t)c * Lq) * Hq + h;
#pragma unroll 16
    for (int s = 0; s < Lq; ++s) {
        float u = fmaf(shx[s], we2, be2);
        float f = u - rintf(u);
        acc = fmaf(om2, f, acc);
        __stcs(hp + (size_t)s * Hq, acc);
    }

    // Output head on the last chunk: acc == ph[b][h].
    if (c == Cq - 1) {
        float ph = acc;
        float t = ph * W_r[2 * Hq + h];
        t = fmaf(cosf(ph), W_r[h], t);
        t = fmaf(sinf(ph), W_r[Hq + h], t);
#pragma unroll
        for (int o = 16; o > 0; o >>= 1)
            t += __shfl_down_sync(0xffffffffu, t, o);
        __shared__ float sh2[2];
        if ((h & 31) == 0) sh2[h >> 5] = t;
        __syncthreads();
        if (h == 0) out[b] = sh2[0] + sh2[1] + b_r[0];
    }
}

extern "C" void kernel_launch(void* const* d_in, const int* in_sizes, int n_in,
                              void* d_out, int out_size) {
    const float* x     = (const float*)d_in[0];
    const float* W_e   = (const float*)d_in[1];
    const float* b_e   = (const float*)d_in[2];
    const float* omega = (const float*)d_in[3];
    const float* W_r   = (const float*)d_in[4];
    const float* b_r   = (const float*)d_in[5];

    float* out  = (float*)d_out;        // out = B floats
    float* hseq = (float*)d_out + Bq;   // then Hseq = B*S*H floats

    k_partials<<<Bq * Cq, Hq>>>(x, W_e, b_e, omega);
    k_scan<<<Bq * Cq, Hq>>>(x, W_e, b_e, omega, W_r, b_r, out, hseq);
}